// round 1
// baseline (speedup 1.0000x reference)
#include <cuda_runtime.h>

#define SEQ 3120
#define DIM 1536
#define NH 12
#define HD 128
#define FRAME 1560
#define NQKV (3*DIM)

// ---------------- scratch (device globals; no allocation allowed) -------------
__device__ float buf_qkv[(size_t)SEQ * NQKV];      // 57.5 MB
__device__ float buf_q[(size_t)NH * SEQ * HD];     // 19.2 MB  [h][s][d]
__device__ float buf_k[(size_t)NH * SEQ * HD];
__device__ float buf_v[(size_t)NH * SEQ * HD];
__device__ float buf_att[(size_t)SEQ * DIM];       // 19.2 MB  [s][h*128+d]

// ---------------- SGEMM: C[M,N] = A[M,K] @ B[K,N] + bias[N] -------------------
// 128x128 block tile, BK=8, 256 threads, 8x8 per-thread microtile.
__global__ void __launch_bounds__(256) sgemm_bias(
    int M, int N, int K,
    const float* __restrict__ A, const float* __restrict__ B,
    const float* __restrict__ bias, float* __restrict__ C)
{
    __shared__ float As[8][128];
    __shared__ float Bs[8][132];

    const int tid = threadIdx.x;
    const int bm = blockIdx.y * 128;
    const int bn = blockIdx.x * 128;
    const int tx = tid & 15;        // 0..15 -> N microtile
    const int ty = tid >> 4;        // 0..15 -> M microtile

    float acc[8][8];
#pragma unroll
    for (int i = 0; i < 8; i++)
#pragma unroll
        for (int j = 0; j < 8; j++) acc[i][j] = 0.f;

    const int arow = tid >> 1;           // 0..127
    const int acol = (tid & 1) << 2;     // 0 or 4
    const int brow = tid >> 5;           // 0..7
    const int bcol = (tid & 31) << 2;    // 0..124

    const bool aval = (bm + arow) < M;
    const float* Aptr = A + (size_t)(bm + arow) * K + acol;
    const float* Bptr = B + (size_t)brow * N + bn + bcol;

    for (int k0 = 0; k0 < K; k0 += 8) {
        float4 av = aval ? *(const float4*)(Aptr + k0)
                         : make_float4(0.f, 0.f, 0.f, 0.f);
        As[acol + 0][arow] = av.x;
        As[acol + 1][arow] = av.y;
        As[acol + 2][arow] = av.z;
        As[acol + 3][arow] = av.w;
        *(float4*)&Bs[brow][bcol] = *(const float4*)(Bptr + (size_t)k0 * N);
        __syncthreads();

#pragma unroll
        for (int kk = 0; kk < 8; kk++) {
            float a[8], b[8];
            *(float4*)&a[0] = *(const float4*)&As[kk][ty * 8];
            *(float4*)&a[4] = *(const float4*)&As[kk][ty * 8 + 4];
            *(float4*)&b[0] = *(const float4*)&Bs[kk][tx * 8];
            *(float4*)&b[4] = *(const float4*)&Bs[kk][tx * 8 + 4];
#pragma unroll
            for (int i = 0; i < 8; i++)
#pragma unroll
                for (int j = 0; j < 8; j++)
                    acc[i][j] += a[i] * b[j];
        }
        __syncthreads();
    }

#pragma unroll
    for (int i = 0; i < 8; i++) {
        const int r = bm + ty * 8 + i;
        if (r < M) {
            float* cp = C + (size_t)r * N + bn + tx * 8;
            const float* bp = bias + bn + tx * 8;
            float4 o0, o1;
            o0.x = acc[i][0] + bp[0]; o0.y = acc[i][1] + bp[1];
            o0.z = acc[i][2] + bp[2]; o0.w = acc[i][3] + bp[3];
            o1.x = acc[i][4] + bp[4]; o1.y = acc[i][5] + bp[5];
            o1.z = acc[i][6] + bp[6]; o1.w = acc[i][7] + bp[7];
            *(float4*)cp = o0;
            *(float4*)(cp + 4) = o1;
        }
    }
}

// ---------------- RMSNorm (over full DIM) + RoPE + layout to [h][s][d] --------
__global__ void __launch_bounds__(256) norm_rope(
    const float* __restrict__ gamma_q, const float* __restrict__ gamma_k,
    const float* __restrict__ cosb, const float* __restrict__ sinb)
{
    const int s = blockIdx.x;
    const int tid = threadIdx.x;
    __shared__ float row[DIM];
    __shared__ float red[8];
    __shared__ float s_scale;

    const float* base = buf_qkv + (size_t)s * NQKV;

    for (int sel = 0; sel < 2; sel++) {
        const float* src = base + sel * DIM;
        const float* gamma = sel ? gamma_k : gamma_q;
        float* dst = sel ? buf_k : buf_q;

        float ss = 0.f;
        for (int j = tid; j < DIM; j += 256) {
            float x = src[j];
            row[j] = x;
            ss += x * x;
        }
#pragma unroll
        for (int off = 16; off > 0; off >>= 1)
            ss += __shfl_xor_sync(0xffffffffu, ss, off);
        if ((tid & 31) == 0) red[tid >> 5] = ss;
        __syncthreads();
        if (tid == 0) {
            float t = 0.f;
#pragma unroll
            for (int w = 0; w < 8; w++) t += red[w];
            s_scale = rsqrtf(t / (float)DIM + 1e-6f);
        }
        __syncthreads();
        const float scale = s_scale;

        for (int j2 = tid; j2 < DIM / 2; j2 += 256) {
            float x1 = row[2 * j2]     * scale * gamma[2 * j2];
            float x2 = row[2 * j2 + 1] * scale * gamma[2 * j2 + 1];
            const int i = j2 & 63;
            const float c  = cosb[s * 64 + i];
            const float sn = sinb[s * 64 + i];
            const int h = (2 * j2) >> 7;
            const int d = (2 * j2) & 127;
            dst[((size_t)h * SEQ + s) * HD + d]     = x1 * c - x2 * sn;
            dst[((size_t)h * SEQ + s) * HD + d + 1] = x1 * sn + x2 * c;
        }
        __syncthreads();   // protect row[]/red[] before next iteration
    }

    // V pass-through with layout change
    const float* srcv = base + 2 * DIM;
    for (int j = tid; j < DIM; j += 256) {
        const int h = j >> 7, d = j & 127;
        buf_v[((size_t)h * SEQ + s) * HD + d] = srcv[j];
    }
}

// ---------------- flash attention, block-causal (frame = 1560) ---------------
// BQ=64, BK=64, 256 threads. Qs/Ks stored d-major [128][68]; V [64][132];
// Ps [64][65]. K and V share a smem buffer (sequential reuse).
#define BQ 64
#define BKT 64
#define QS_STRIDE 68
#define VS_STRIDE 132
#define PS_STRIDE 65
#define FLASH_SMEM ((128*QS_STRIDE + 128*QS_STRIDE + BQ*PS_STRIDE) * 4)

__global__ void __launch_bounds__(256) flash_attn()
{
    extern __shared__ float sm[];
    float* Qs = sm;                        // [128][68]
    float* KV = sm + 128 * QS_STRIDE;      // K as [128][68] or V as [64][132]
    float* Ps = sm + 2 * 128 * QS_STRIDE;  // [64][65]

    const int h  = blockIdx.y;
    const int q0 = blockIdx.x * BQ;
    const int tid = threadIdx.x;
    const int tx = tid & 15;
    const int ty = tid >> 4;

    const float* Qg = buf_q + (size_t)h * SEQ * HD;
    const float* Kg = buf_k + (size_t)h * SEQ * HD;
    const float* Vg = buf_v + (size_t)h * SEQ * HD;

    // load Q tile transposed: Qs[d][r]
    for (int idx = tid; idx < BQ * 32; idx += 256) {
        const int r = idx >> 5;
        const int dq = (idx & 31) << 2;
        const int s = q0 + r;
        float4 v = (s < SEQ) ? *(const float4*)(Qg + (size_t)s * HD + dq)
                             : make_float4(0.f, 0.f, 0.f, 0.f);
        Qs[(dq + 0) * QS_STRIDE + r] = v.x;
        Qs[(dq + 1) * QS_STRIDE + r] = v.y;
        Qs[(dq + 2) * QS_STRIDE + r] = v.z;
        Qs[(dq + 3) * QS_STRIDE + r] = v.w;
    }

    float O[4][8];
#pragma unroll
    for (int i = 0; i < 4; i++)
#pragma unroll
        for (int c = 0; c < 8; c++) O[i][c] = 0.f;
    float m_i[4], l_i[4];
#pragma unroll
    for (int i = 0; i < 4; i++) { m_i[i] = -1e30f; l_i[i] = 0.f; }

    int rlim[4];
#pragma unroll
    for (int i = 0; i < 4; i++) {
        const int s = q0 + ty * 4 + i;
        int lim = (s / FRAME + 1) * FRAME;
        rlim[i] = lim < SEQ ? lim : SEQ;
    }
    int kmax = ((q0 + BQ - 1) / FRAME + 1) * FRAME;
    if (kmax > SEQ) kmax = SEQ;

    __syncthreads();

    const float sc = 0.08838834764831845f;  // 1/sqrt(128)

    for (int k0 = 0; k0 < kmax; k0 += BKT) {
        // load K tile transposed: KV[d][r]
        for (int idx = tid; idx < BKT * 32; idx += 256) {
            const int r = idx >> 5;
            const int dq = (idx & 31) << 2;
            const int s = k0 + r;
            float4 v = (s < SEQ) ? *(const float4*)(Kg + (size_t)s * HD + dq)
                                 : make_float4(0.f, 0.f, 0.f, 0.f);
            KV[(dq + 0) * QS_STRIDE + r] = v.x;
            KV[(dq + 1) * QS_STRIDE + r] = v.y;
            KV[(dq + 2) * QS_STRIDE + r] = v.z;
            KV[(dq + 3) * QS_STRIDE + r] = v.w;
        }
        __syncthreads();

        // S = Q K^T (4x4 per thread)
        float s_[4][4];
#pragma unroll
        for (int i = 0; i < 4; i++)
#pragma unroll
            for (int j = 0; j < 4; j++) s_[i][j] = 0.f;

#pragma unroll 8
        for (int d = 0; d < HD; d++) {
            float4 a = *(const float4*)(Qs + d * QS_STRIDE + ty * 4);
            float4 b = *(const float4*)(KV + d * QS_STRIDE + tx * 4);
            s_[0][0] += a.x * b.x; s_[0][1] += a.x * b.y; s_[0][2] += a.x * b.z; s_[0][3] += a.x * b.w;
            s_[1][0] += a.y * b.x; s_[1][1] += a.y * b.y; s_[1][2] += a.y * b.z; s_[1][3] += a.y * b.w;
            s_[2][0] += a.z * b.x; s_[2][1] += a.z * b.y; s_[2][2] += a.z * b.z; s_[2][3] += a.z * b.w;
            s_[3][0] += a.w * b.x; s_[3][1] += a.w * b.y; s_[3][2] += a.w * b.z; s_[3][3] += a.w * b.w;
        }

        // scale + mask
#pragma unroll
        for (int i = 0; i < 4; i++)
#pragma unroll
            for (int j = 0; j < 4; j++) {
                const int kc = k0 + tx * 4 + j;
                float v = s_[i][j] * sc;
                s_[i][j] = (kc >= rlim[i]) ? -1e30f : v;
            }

        // online softmax: row max over the 16-lane tx group
        float mnew[4], alpha[4], lt[4];
#pragma unroll
        for (int i = 0; i < 4; i++) {
            float mt = fmaxf(fmaxf(s_[i][0], s_[i][1]), fmaxf(s_[i][2], s_[i][3]));
#pragma unroll
            for (int off = 1; off < 16; off <<= 1)
                mt = fmaxf(mt, __shfl_xor_sync(0xffffffffu, mt, off));
            mnew[i] = fmaxf(m_i[i], mt);
            alpha[i] = __expf(m_i[i] - mnew[i]);
            float ls = 0.f;
#pragma unroll
            for (int j = 0; j < 4; j++) {
                float p = (s_[i][j] <= -1e29f) ? 0.f : __expf(s_[i][j] - mnew[i]);
                s_[i][j] = p;
                ls += p;
            }
#pragma unroll
            for (int off = 1; off < 16; off <<= 1)
                ls += __shfl_xor_sync(0xffffffffu, ls, off);
            lt[i] = ls;
        }
#pragma unroll
        for (int i = 0; i < 4; i++) {
            l_i[i] = l_i[i] * alpha[i] + lt[i];
            m_i[i] = mnew[i];
#pragma unroll
            for (int c = 0; c < 8; c++) O[i][c] *= alpha[i];
            // store P
#pragma unroll
            for (int j = 0; j < 4; j++)
                Ps[(ty * 4 + i) * PS_STRIDE + tx * 4 + j] = s_[i][j];
        }
        __syncthreads();   // everyone done reading K (and writing P)

        // load V tile over K's smem: KV[r][d], stride 132
        for (int idx = tid; idx < BKT * 32; idx += 256) {
            const int r = idx >> 5;
            const int dq = (idx & 31) << 2;
            const int s = k0 + r;
            float4 v = (s < SEQ) ? *(const float4*)(Vg + (size_t)s * HD + dq)
                                 : make_float4(0.f, 0.f, 0.f, 0.f);
            *(float4*)(KV + r * VS_STRIDE + dq) = v;
        }
        __syncthreads();

        // O += P @ V
#pragma unroll 4
        for (int k = 0; k < BKT; k++) {
            float pv[4];
#pragma unroll
            for (int i = 0; i < 4; i++)
                pv[i] = Ps[(ty * 4 + i) * PS_STRIDE + k];
            float4 v0 = *(const float4*)(KV + k * VS_STRIDE + tx * 8);
            float4 v1 = *(const float4*)(KV + k * VS_STRIDE + tx * 8 + 4);
#pragma unroll
            for (int i = 0; i < 4; i++) {
                O[i][0] += pv[i] * v0.x; O[i][1] += pv[i] * v0.y;
                O[i][2] += pv[i] * v0.z; O[i][3] += pv[i] * v0.w;
                O[i][4] += pv[i] * v1.x; O[i][5] += pv[i] * v1.y;
                O[i][6] += pv[i] * v1.z; O[i][7] += pv[i] * v1.w;
            }
        }
        __syncthreads();   // before next tile overwrites KV / Ps
    }

    // epilogue: O / l -> buf_att[s][h*128 + c]
#pragma unroll
    for (int i = 0; i < 4; i++) {
        const int s = q0 + ty * 4 + i;
        if (s < SEQ) {
            const float inv = 1.f / l_i[i];
            float* op = buf_att + (size_t)s * DIM + h * HD + tx * 8;
            float4 o0, o1;
            o0.x = O[i][0] * inv; o0.y = O[i][1] * inv;
            o0.z = O[i][2] * inv; o0.w = O[i][3] * inv;
            o1.x = O[i][4] * inv; o1.y = O[i][5] * inv;
            o1.z = O[i][6] * inv; o1.w = O[i][7] * inv;
            *(float4*)op = o0;
            *(float4*)(op + 4) = o1;
        }
    }
}

// ---------------- launch ------------------------------------------------------
extern "C" void kernel_launch(void* const* d_in, const int* in_sizes, int n_in,
                              void* d_out, int out_size)
{
    const float* hidden  = (const float*)d_in[0];
    const float* cosb    = (const float*)d_in[1];
    const float* sinb    = (const float*)d_in[2];
    const float* w_qkv   = (const float*)d_in[3];
    const float* b_qkv   = (const float*)d_in[4];
    const float* gamma_q = (const float*)d_in[5];
    const float* gamma_k = (const float*)d_in[6];
    const float* w_out   = (const float*)d_in[7];
    const float* b_out   = (const float*)d_in[8];
    float* out = (float*)d_out;

    float *qkv_p, *att_p;
    cudaGetSymbolAddress((void**)&qkv_p, buf_qkv);
    cudaGetSymbolAddress((void**)&att_p, buf_att);

    // 1) QKV projection
    dim3 g1(NQKV / 128, (SEQ + 127) / 128);
    sgemm_bias<<<g1, 256>>>(SEQ, NQKV, DIM, hidden, w_qkv, b_qkv, qkv_p);

    // 2) RMSNorm + RoPE + relayout
    norm_rope<<<SEQ, 256>>>(gamma_q, gamma_k, cosb, sinb);

    // 3) attention
    cudaFuncSetAttribute(flash_attn, cudaFuncAttributeMaxDynamicSharedMemorySize,
                         FLASH_SMEM);
    dim3 g3((SEQ + BQ - 1) / BQ, NH);
    flash_attn<<<g3, 256, FLASH_SMEM>>>();

    // 4) output projection
    dim3 g4(DIM / 128, (SEQ + 127) / 128);
    sgemm_bias<<<g4, 256>>>(SEQ, DIM, DIM, att_p, w_out, b_out, out);
}

// round 2
// speedup vs baseline: 2.4572x; 2.4572x over previous
#include <cuda_runtime.h>
#include <cstdint>

#define SEQ 3120
#define DIM 1536
#define NH 12
#define HD 128
#define FRAME 1560
#define NQKV (3*DIM)

// ---------------- scratch (device globals; no allocation allowed) -------------
__device__ float buf_qkv[(size_t)SEQ * NQKV];
__device__ float buf_q[(size_t)NH * SEQ * HD];     // [h][s][d]
__device__ float buf_k[(size_t)NH * SEQ * HD];
__device__ float buf_v[(size_t)NH * SEQ * HD];
__device__ float buf_att[(size_t)SEQ * DIM];       // [s][h*128+d]

// ---------------- tf32 helpers ------------------------------------------------
__device__ __forceinline__ uint32_t f2tf(float x) {
    uint32_t u;
    asm("cvt.rna.tf32.f32 %0, %1;" : "=r"(u) : "f"(x));
    return u;
}

__device__ __forceinline__ void mma8(float* d, const uint32_t* a, const uint32_t* b) {
    asm volatile(
        "mma.sync.aligned.m16n8k8.row.col.f32.tf32.tf32.f32 "
        "{%0,%1,%2,%3},{%4,%5,%6,%7},{%8,%9},{%0,%1,%2,%3};"
        : "+f"(d[0]), "+f"(d[1]), "+f"(d[2]), "+f"(d[3])
        : "r"(a[0]), "r"(a[1]), "r"(a[2]), "r"(a[3]), "r"(b[0]), "r"(b[1]));
}

// ---------------- TF32 GEMM: C[M,N] = A[M,K] @ B[K,N] + bias ------------------
// 128x128x32 block tile, 256 threads (8 warps, 2x4; warp tile 64x32).
// smem k-major, stride 136 (conflict-free frag loads), double buffered.
#define GK 32
#define GST 136
#define GEMM_SMEM (4 * GK * GST * 4)   // 2 bufs * (A + B) tiles

__global__ void __launch_bounds__(256) gemm_tf32(
    int M, int N, int K,
    const float* __restrict__ A, const float* __restrict__ B,
    const float* __restrict__ bias, float* __restrict__ C)
{
    extern __shared__ uint32_t smg[];
    uint32_t* As = smg;                 // [2][32][136]
    uint32_t* Bs = smg + 2 * GK * GST;  // [2][32][136]

    const int tid = threadIdx.x;
    const int wid = tid >> 5, lane = tid & 31;
    const int g = lane >> 2, t = lane & 3;
    const int bm = blockIdx.y * 128, bn = blockIdx.x * 128;
    const int warpm = (wid >> 2) * 64, warpn = (wid & 3) * 32;

    // loader mapping
    const int am = tid & 127;            // A row
    const int ah = tid >> 7;             // A k half (0/1)
    const int bkb = tid >> 5;            // B k row (0..7)
    const int bn4 = lane << 2;           // B col
    const bool avalid = (bm + am) < M;
    const float* Ap = A + (size_t)(bm + am) * K + ah * 16;
    const float* Bp = B + (size_t)bkb * N + bn + bn4;

    float acc[4][4][4];
#pragma unroll
    for (int i = 0; i < 4; i++)
#pragma unroll
        for (int j = 0; j < 4; j++)
#pragma unroll
            for (int c = 0; c < 4; c++) acc[i][j][c] = 0.f;

    const int KT = K / GK;

    // preload tile 0
    {
#pragma unroll
        for (int ii = 0; ii < 4; ii++) {
            float4 v = avalid ? *(const float4*)(Ap + ii * 4)
                              : make_float4(0.f, 0.f, 0.f, 0.f);
            const int k = ah * 16 + ii * 4;
            As[(k + 0) * GST + am] = f2tf(v.x);
            As[(k + 1) * GST + am] = f2tf(v.y);
            As[(k + 2) * GST + am] = f2tf(v.z);
            As[(k + 3) * GST + am] = f2tf(v.w);
        }
#pragma unroll
        for (int ii = 0; ii < 4; ii++) {
            float4 v = *(const float4*)(Bp + (size_t)(ii * 8) * N);
            uint32_t* p = Bs + (bkb + ii * 8) * GST + bn4;
            p[0] = f2tf(v.x); p[1] = f2tf(v.y); p[2] = f2tf(v.z); p[3] = f2tf(v.w);
        }
    }
    __syncthreads();

    int buf = 0;
    for (int kt = 0; kt < KT; kt++) {
        float4 ra[4], rb[4];
        const bool pf = (kt + 1) < KT;
        if (pf) {
            const float* Ap2 = Ap + (kt + 1) * GK;
            const float* Bp2 = Bp + (size_t)(kt + 1) * GK * N;
#pragma unroll
            for (int ii = 0; ii < 4; ii++)
                ra[ii] = avalid ? *(const float4*)(Ap2 + ii * 4)
                                : make_float4(0.f, 0.f, 0.f, 0.f);
#pragma unroll
            for (int ii = 0; ii < 4; ii++)
                rb[ii] = *(const float4*)(Bp2 + (size_t)(ii * 8) * N);
        }

        const uint32_t* Ab = As + buf * GK * GST;
        const uint32_t* Bb = Bs + buf * GK * GST;
#pragma unroll
        for (int kk = 0; kk < 4; kk++) {
            const int k8 = kk * 8;
            uint32_t af[4][4], bf[4][2];
#pragma unroll
            for (int i = 0; i < 4; i++) {
                const uint32_t* r0 = Ab + (k8 + t) * GST + warpm + i * 16 + g;
                const uint32_t* r1 = Ab + (k8 + t + 4) * GST + warpm + i * 16 + g;
                af[i][0] = r0[0]; af[i][1] = r0[8];
                af[i][2] = r1[0]; af[i][3] = r1[8];
            }
#pragma unroll
            for (int j = 0; j < 4; j++) {
                bf[j][0] = Bb[(k8 + t) * GST + warpn + j * 8 + g];
                bf[j][1] = Bb[(k8 + t + 4) * GST + warpn + j * 8 + g];
            }
#pragma unroll
            for (int i = 0; i < 4; i++)
#pragma unroll
                for (int j = 0; j < 4; j++)
                    mma8(acc[i][j], af[i], bf[j]);
        }

        if (pf) {
            const int nb = buf ^ 1;
            uint32_t* Aw = As + nb * GK * GST;
            uint32_t* Bw = Bs + nb * GK * GST;
#pragma unroll
            for (int ii = 0; ii < 4; ii++) {
                const int k = ah * 16 + ii * 4;
                Aw[(k + 0) * GST + am] = f2tf(ra[ii].x);
                Aw[(k + 1) * GST + am] = f2tf(ra[ii].y);
                Aw[(k + 2) * GST + am] = f2tf(ra[ii].z);
                Aw[(k + 3) * GST + am] = f2tf(ra[ii].w);
            }
#pragma unroll
            for (int ii = 0; ii < 4; ii++) {
                uint32_t* p = Bw + (bkb + ii * 8) * GST + bn4;
                p[0] = f2tf(rb[ii].x); p[1] = f2tf(rb[ii].y);
                p[2] = f2tf(rb[ii].z); p[3] = f2tf(rb[ii].w);
            }
            __syncthreads();
            buf = nb;
        }
    }

    // epilogue with bias
#pragma unroll
    for (int i = 0; i < 4; i++) {
        const int r0 = bm + warpm + i * 16 + g;
#pragma unroll
        for (int j = 0; j < 4; j++) {
            const int c0 = bn + warpn + j * 8 + 2 * t;
            const float b0 = bias[c0], b1 = bias[c0 + 1];
            if (r0 < M) {
                float2 v; v.x = acc[i][j][0] + b0; v.y = acc[i][j][1] + b1;
                *(float2*)(C + (size_t)r0 * N + c0) = v;
            }
            if (r0 + 8 < M) {
                float2 v; v.x = acc[i][j][2] + b0; v.y = acc[i][j][3] + b1;
                *(float2*)(C + (size_t)(r0 + 8) * N + c0) = v;
            }
        }
    }
}

// ---------------- RMSNorm (over full DIM) + RoPE + layout to [h][s][d] --------
__global__ void __launch_bounds__(256) norm_rope(
    const float* __restrict__ gamma_q, const float* __restrict__ gamma_k,
    const float* __restrict__ cosb, const float* __restrict__ sinb)
{
    const int s = blockIdx.x;
    const int tid = threadIdx.x;
    __shared__ float row[DIM];
    __shared__ float red[8];
    __shared__ float s_scale;

    const float* base = buf_qkv + (size_t)s * NQKV;

    for (int sel = 0; sel < 2; sel++) {
        const float* src = base + sel * DIM;
        const float* gamma = sel ? gamma_k : gamma_q;
        float* dst = sel ? buf_k : buf_q;

        float ss = 0.f;
        for (int j = tid; j < DIM; j += 256) {
            float x = src[j];
            row[j] = x;
            ss += x * x;
        }
#pragma unroll
        for (int off = 16; off > 0; off >>= 1)
            ss += __shfl_xor_sync(0xffffffffu, ss, off);
        if ((tid & 31) == 0) red[tid >> 5] = ss;
        __syncthreads();
        if (tid == 0) {
            float tt = 0.f;
#pragma unroll
            for (int wq = 0; wq < 8; wq++) tt += red[wq];
            s_scale = rsqrtf(tt / (float)DIM + 1e-6f);
        }
        __syncthreads();
        const float scale = s_scale;

        for (int j2 = tid; j2 < DIM / 2; j2 += 256) {
            float x1 = row[2 * j2]     * scale * gamma[2 * j2];
            float x2 = row[2 * j2 + 1] * scale * gamma[2 * j2 + 1];
            const int i = j2 & 63;
            const float c  = cosb[s * 64 + i];
            const float sn = sinb[s * 64 + i];
            const int h = (2 * j2) >> 7;
            const int d = (2 * j2) & 127;
            dst[((size_t)h * SEQ + s) * HD + d]     = x1 * c - x2 * sn;
            dst[((size_t)h * SEQ + s) * HD + d + 1] = x1 * sn + x2 * c;
        }
        __syncthreads();
    }

    const float* srcv = base + 2 * DIM;
    for (int j = tid; j < DIM; j += 256) {
        const int h = j >> 7, d = j & 127;
        buf_v[((size_t)h * SEQ + s) * HD + d] = srcv[j];
    }
}

// ---------------- TF32 flash attention, block-causal --------------------------
// BQ=64, BK=64, 128 threads (4 warps, 16 q-rows each). Q in registers (tf32
// a-frags, pre-scaled). K/V share one smem buffer; P re-fragments via smem.
#define ATT_BQ 64
#define KVST 132
#define PST 68
#define ATT_SMEM ((64 * KVST + 64 * PST) * 4)

__global__ void __launch_bounds__(128) flash_tf32()
{
    extern __shared__ uint32_t sma[];
    uint32_t* KVs = sma;                // [64][132]
    uint32_t* Ps  = sma + 64 * KVST;    // [64][68]

    const int h = blockIdx.y;
    const int q0 = blockIdx.x * ATT_BQ;
    const int tid = threadIdx.x, w = tid >> 5, lane = tid & 31;
    const int g = lane >> 2, t = lane & 3;

    const float* Qg = buf_q + (size_t)h * SEQ * HD;
    const float* Kg = buf_k + (size_t)h * SEQ * HD;
    const float* Vg = buf_v + (size_t)h * SEQ * HD;

    const int r0 = q0 + w * 16 + g, r1 = r0 + 8;
    const int lr0 = w * 16 + g, lr1 = lr0 + 8;
    const float sc = 0.08838834764831845f;   // 1/sqrt(128)

    // Q a-frags, pre-scaled, tf32 (HD/8 = 16 k-steps)
    uint32_t qa[16][4];
#pragma unroll
    for (int ks = 0; ks < 16; ks++) {
        const int k8 = ks * 8;
        qa[ks][0] = (r0 < SEQ) ? f2tf(Qg[(size_t)r0 * HD + k8 + t] * sc) : 0u;
        qa[ks][1] = (r1 < SEQ) ? f2tf(Qg[(size_t)r1 * HD + k8 + t] * sc) : 0u;
        qa[ks][2] = (r0 < SEQ) ? f2tf(Qg[(size_t)r0 * HD + k8 + t + 4] * sc) : 0u;
        qa[ks][3] = (r1 < SEQ) ? f2tf(Qg[(size_t)r1 * HD + k8 + t + 4] * sc) : 0u;
    }

    float O[16][4];
#pragma unroll
    for (int j = 0; j < 16; j++)
#pragma unroll
        for (int c = 0; c < 4; c++) O[j][c] = 0.f;
    float m0 = -1e30f, m1 = -1e30f, l0 = 0.f, l1 = 0.f;

    int rl0 = (r0 / FRAME + 1) * FRAME; if (rl0 > SEQ) rl0 = SEQ;
    int rl1 = (r1 / FRAME + 1) * FRAME; if (rl1 > SEQ) rl1 = SEQ;
    int qlast = q0 + ATT_BQ - 1; if (qlast > SEQ - 1) qlast = SEQ - 1;
    int kmax = (qlast / FRAME + 1) * FRAME; if (kmax > SEQ) kmax = SEQ;

    for (int k0 = 0; k0 < kmax; k0 += 64) {
        // load K tile (cvt to tf32): KVs[key][d]
        for (int idx = tid; idx < 64 * 32; idx += 128) {
            const int r = idx >> 5, c4 = (idx & 31) << 2;
            const int srow = k0 + r;
            float4 v = (srow < SEQ) ? *(const float4*)(Kg + (size_t)srow * HD + c4)
                                    : make_float4(0.f, 0.f, 0.f, 0.f);
            uint32_t* p = KVs + r * KVST + c4;
            p[0] = f2tf(v.x); p[1] = f2tf(v.y); p[2] = f2tf(v.z); p[3] = f2tf(v.w);
        }
        __syncthreads();

        // S = Q K^T (per warp: 16 rows x 64 cols, 8 n-tiles)
        float sf[8][4];
#pragma unroll
        for (int j = 0; j < 8; j++)
#pragma unroll
            for (int c = 0; c < 4; c++) sf[j][c] = 0.f;

#pragma unroll
        for (int ks = 0; ks < 16; ks++) {
            const int k8 = ks * 8;
#pragma unroll
            for (int j = 0; j < 8; j++) {
                uint32_t bf[2];
                const uint32_t* kp = KVs + (j * 8 + g) * KVST + k8 + t;
                bf[0] = kp[0]; bf[1] = kp[4];
                mma8(sf[j], qa[ks], bf);
            }
        }

        // mask + online softmax
        float mt0 = -1e30f, mt1 = -1e30f;
#pragma unroll
        for (int j = 0; j < 8; j++) {
            const int c = k0 + j * 8 + 2 * t;
            sf[j][0] = (c     < rl0) ? sf[j][0] : -1e30f;
            sf[j][1] = (c + 1 < rl0) ? sf[j][1] : -1e30f;
            sf[j][2] = (c     < rl1) ? sf[j][2] : -1e30f;
            sf[j][3] = (c + 1 < rl1) ? sf[j][3] : -1e30f;
            mt0 = fmaxf(mt0, fmaxf(sf[j][0], sf[j][1]));
            mt1 = fmaxf(mt1, fmaxf(sf[j][2], sf[j][3]));
        }
        mt0 = fmaxf(mt0, __shfl_xor_sync(0xffffffffu, mt0, 1));
        mt0 = fmaxf(mt0, __shfl_xor_sync(0xffffffffu, mt0, 2));
        mt1 = fmaxf(mt1, __shfl_xor_sync(0xffffffffu, mt1, 1));
        mt1 = fmaxf(mt1, __shfl_xor_sync(0xffffffffu, mt1, 2));

        const float mn0 = fmaxf(m0, mt0), mn1 = fmaxf(m1, mt1);
        const float a0 = __expf(m0 - mn0), a1 = __expf(m1 - mn1);
        float s0 = 0.f, s1 = 0.f;
#pragma unroll
        for (int j = 0; j < 8; j++) {
            float p0 = __expf(sf[j][0] - mn0);
            float p1 = __expf(sf[j][1] - mn0);
            float p2 = __expf(sf[j][2] - mn1);
            float p3 = __expf(sf[j][3] - mn1);
            s0 += p0 + p1; s1 += p2 + p3;
            uint32_t* pp0 = Ps + lr0 * PST + j * 8 + 2 * t;
            uint32_t* pp1 = Ps + lr1 * PST + j * 8 + 2 * t;
            pp0[0] = f2tf(p0); pp0[1] = f2tf(p1);
            pp1[0] = f2tf(p2); pp1[1] = f2tf(p3);
        }
        s0 += __shfl_xor_sync(0xffffffffu, s0, 1);
        s0 += __shfl_xor_sync(0xffffffffu, s0, 2);
        s1 += __shfl_xor_sync(0xffffffffu, s1, 1);
        s1 += __shfl_xor_sync(0xffffffffu, s1, 2);
        l0 = l0 * a0 + s0;  m0 = mn0;
        l1 = l1 * a1 + s1;  m1 = mn1;
#pragma unroll
        for (int j = 0; j < 16; j++) {
            O[j][0] *= a0; O[j][1] *= a0;
            O[j][2] *= a1; O[j][3] *= a1;
        }
        __syncthreads();   // all warps done reading K

        // load V tile (cvt to tf32) over KVs
        for (int idx = tid; idx < 64 * 32; idx += 128) {
            const int r = idx >> 5, c4 = (idx & 31) << 2;
            const int srow = k0 + r;
            float4 v = (srow < SEQ) ? *(const float4*)(Vg + (size_t)srow * HD + c4)
                                    : make_float4(0.f, 0.f, 0.f, 0.f);
            uint32_t* p = KVs + r * KVST + c4;
            p[0] = f2tf(v.x); p[1] = f2tf(v.y); p[2] = f2tf(v.z); p[3] = f2tf(v.w);
        }
        __syncthreads();

        // O += P @ V
#pragma unroll
        for (int kk = 0; kk < 8; kk++) {
            const int k8 = kk * 8;
            uint32_t af[4];
            const uint32_t* p0 = Ps + lr0 * PST + k8 + t;
            const uint32_t* p1 = Ps + lr1 * PST + k8 + t;
            af[0] = p0[0]; af[1] = p1[0]; af[2] = p0[4]; af[3] = p1[4];
#pragma unroll
            for (int j = 0; j < 16; j++) {
                uint32_t bf[2];
                const uint32_t* vp = KVs + (k8 + t) * KVST + j * 8 + g;
                bf[0] = vp[0]; bf[1] = vp[4 * KVST];
                mma8(O[j], af, bf);
            }
        }
        __syncthreads();   // before next tile overwrites KVs
    }

    // epilogue
    const float inv0 = 1.f / l0, inv1 = 1.f / l1;
#pragma unroll
    for (int j = 0; j < 16; j++) {
        const int c = h * HD + j * 8 + 2 * t;
        if (r0 < SEQ) {
            float2 v; v.x = O[j][0] * inv0; v.y = O[j][1] * inv0;
            *(float2*)(buf_att + (size_t)r0 * DIM + c) = v;
        }
        if (r1 < SEQ) {
            float2 v; v.x = O[j][2] * inv1; v.y = O[j][3] * inv1;
            *(float2*)(buf_att + (size_t)r1 * DIM + c) = v;
        }
    }
}

// ---------------- launch ------------------------------------------------------
extern "C" void kernel_launch(void* const* d_in, const int* in_sizes, int n_in,
                              void* d_out, int out_size)
{
    const float* hidden  = (const float*)d_in[0];
    const float* cosb    = (const float*)d_in[1];
    const float* sinb    = (const float*)d_in[2];
    const float* w_qkv   = (const float*)d_in[3];
    const float* b_qkv   = (const float*)d_in[4];
    const float* gamma_q = (const float*)d_in[5];
    const float* gamma_k = (const float*)d_in[6];
    const float* w_out   = (const float*)d_in[7];
    const float* b_out   = (const float*)d_in[8];
    float* out = (float*)d_out;

    float *qkv_p, *att_p;
    cudaGetSymbolAddress((void**)&qkv_p, buf_qkv);
    cudaGetSymbolAddress((void**)&att_p, buf_att);

    cudaFuncSetAttribute(gemm_tf32, cudaFuncAttributeMaxDynamicSharedMemorySize,
                         GEMM_SMEM);
    cudaFuncSetAttribute(flash_tf32, cudaFuncAttributeMaxDynamicSharedMemorySize,
                         ATT_SMEM);

    // 1) QKV projection
    dim3 g1(NQKV / 128, (SEQ + 127) / 128);
    gemm_tf32<<<g1, 256, GEMM_SMEM>>>(SEQ, NQKV, DIM, hidden, w_qkv, b_qkv, qkv_p);

    // 2) RMSNorm + RoPE + relayout
    norm_rope<<<SEQ, 256>>>(gamma_q, gamma_k, cosb, sinb);

    // 3) attention
    dim3 g3((SEQ + ATT_BQ - 1) / ATT_BQ, NH);
    flash_tf32<<<g3, 128, ATT_SMEM>>>();

    // 4) output projection
    dim3 g4(DIM / 128, (SEQ + 127) / 128);
    gemm_tf32<<<g4, 256, GEMM_SMEM>>>(SEQ, DIM, DIM, att_p, w_out, b_out, out);
}

// round 3
// speedup vs baseline: 2.7401x; 1.1151x over previous
#include <cuda_runtime.h>
#include <cstdint>

#define SEQ 3120
#define DIM 1536
#define NH 12
#define HD 128
#define FRAME 1560
#define NQKV (3*DIM)

// ---------------- scratch (device globals; no allocation allowed) -------------
__device__ float buf_qkv[(size_t)SEQ * NQKV];
__device__ float buf_q[(size_t)NH * SEQ * HD];     // [h][s][d]
__device__ float buf_k[(size_t)NH * SEQ * HD];
__device__ float buf_v[(size_t)NH * SEQ * HD];
__device__ float buf_att[(size_t)SEQ * DIM];       // [s][h*128+d]

// ---------------- tf32 helpers ------------------------------------------------
__device__ __forceinline__ uint32_t f2tf(float x) {
    uint32_t u;
    asm("cvt.rna.tf32.f32 %0, %1;" : "=r"(u) : "f"(x));
    return u;
}

__device__ __forceinline__ void mma8(float* d, const uint32_t* a, const uint32_t* b) {
    asm volatile(
        "mma.sync.aligned.m16n8k8.row.col.f32.tf32.tf32.f32 "
        "{%0,%1,%2,%3},{%4,%5,%6,%7},{%8,%9},{%0,%1,%2,%3};"
        : "+f"(d[0]), "+f"(d[1]), "+f"(d[2]), "+f"(d[3])
        : "r"(a[0]), "r"(a[1]), "r"(a[2]), "r"(a[3]), "r"(b[0]), "r"(b[1]));
}

// ---------------- TF32 GEMM: C[M,N] = A[M,K] @ B[K,N] + bias ------------------
// 128x128x32 block tile, 256 threads (8 warps, 2x4; warp tile 64x32).
// smem k-major, stride 136 (conflict-free frag loads), double buffered.
// __launch_bounds__(256,2): cap regs at 128 so 2 CTAs fit per SM.
#define GK 32
#define GST 136
#define GEMM_SMEM (4 * GK * GST * 4)   // 2 bufs * (A + B) tiles

__global__ void __launch_bounds__(256, 2) gemm_tf32(
    int M, int N, int K,
    const float* __restrict__ A, const float* __restrict__ B,
    const float* __restrict__ bias, float* __restrict__ C)
{
    extern __shared__ uint32_t smg[];
    uint32_t* As = smg;                 // [2][32][136]
    uint32_t* Bs = smg + 2 * GK * GST;  // [2][32][136]

    const int tid = threadIdx.x;
    const int wid = tid >> 5, lane = tid & 31;
    const int g = lane >> 2, t = lane & 3;
    const int bm = blockIdx.y * 128, bn = blockIdx.x * 128;
    const int warpm = (wid >> 2) * 64, warpn = (wid & 3) * 32;

    // loader mapping
    const int am = tid & 127;            // A row
    const int ah = tid >> 7;             // A k half (0/1)
    const int bkb = tid >> 5;            // B k row (0..7)
    const int bn4 = lane << 2;           // B col
    const bool avalid = (bm + am) < M;
    const float* Ap = A + (size_t)(bm + am) * K + ah * 16;
    const float* Bp = B + (size_t)bkb * N + bn + bn4;

    float acc[4][4][4];
#pragma unroll
    for (int i = 0; i < 4; i++)
#pragma unroll
        for (int j = 0; j < 4; j++)
#pragma unroll
            for (int c = 0; c < 4; c++) acc[i][j][c] = 0.f;

    const int KT = K / GK;

    // preload tile 0
    {
#pragma unroll
        for (int ii = 0; ii < 4; ii++) {
            float4 v = avalid ? *(const float4*)(Ap + ii * 4)
                              : make_float4(0.f, 0.f, 0.f, 0.f);
            const int k = ah * 16 + ii * 4;
            As[(k + 0) * GST + am] = f2tf(v.x);
            As[(k + 1) * GST + am] = f2tf(v.y);
            As[(k + 2) * GST + am] = f2tf(v.z);
            As[(k + 3) * GST + am] = f2tf(v.w);
        }
#pragma unroll
        for (int ii = 0; ii < 4; ii++) {
            float4 v = *(const float4*)(Bp + (size_t)(ii * 8) * N);
            uint32_t* p = Bs + (bkb + ii * 8) * GST + bn4;
            p[0] = f2tf(v.x); p[1] = f2tf(v.y); p[2] = f2tf(v.z); p[3] = f2tf(v.w);
        }
    }
    __syncthreads();

    int buf = 0;
    for (int kt = 0; kt < KT; kt++) {
        float4 ra[4], rb[4];
        const bool pf = (kt + 1) < KT;
        if (pf) {
            const float* Ap2 = Ap + (kt + 1) * GK;
            const float* Bp2 = Bp + (size_t)(kt + 1) * GK * N;
#pragma unroll
            for (int ii = 0; ii < 4; ii++)
                ra[ii] = avalid ? *(const float4*)(Ap2 + ii * 4)
                                : make_float4(0.f, 0.f, 0.f, 0.f);
#pragma unroll
            for (int ii = 0; ii < 4; ii++)
                rb[ii] = *(const float4*)(Bp2 + (size_t)(ii * 8) * N);
        }

        const uint32_t* Ab = As + buf * GK * GST;
        const uint32_t* Bb = Bs + buf * GK * GST;
#pragma unroll
        for (int kk = 0; kk < 4; kk++) {
            const int k8 = kk * 8;
            uint32_t af[4][4], bf[4][2];
#pragma unroll
            for (int i = 0; i < 4; i++) {
                const uint32_t* r0 = Ab + (k8 + t) * GST + warpm + i * 16 + g;
                const uint32_t* r1 = Ab + (k8 + t + 4) * GST + warpm + i * 16 + g;
                af[i][0] = r0[0]; af[i][1] = r0[8];
                af[i][2] = r1[0]; af[i][3] = r1[8];
            }
#pragma unroll
            for (int j = 0; j < 4; j++) {
                bf[j][0] = Bb[(k8 + t) * GST + warpn + j * 8 + g];
                bf[j][1] = Bb[(k8 + t + 4) * GST + warpn + j * 8 + g];
            }
#pragma unroll
            for (int i = 0; i < 4; i++)
#pragma unroll
                for (int j = 0; j < 4; j++)
                    mma8(acc[i][j], af[i], bf[j]);
        }

        if (pf) {
            const int nb = buf ^ 1;
            uint32_t* Aw = As + nb * GK * GST;
            uint32_t* Bw = Bs + nb * GK * GST;
#pragma unroll
            for (int ii = 0; ii < 4; ii++) {
                const int k = ah * 16 + ii * 4;
                Aw[(k + 0) * GST + am] = f2tf(ra[ii].x);
                Aw[(k + 1) * GST + am] = f2tf(ra[ii].y);
                Aw[(k + 2) * GST + am] = f2tf(ra[ii].z);
                Aw[(k + 3) * GST + am] = f2tf(ra[ii].w);
            }
#pragma unroll
            for (int ii = 0; ii < 4; ii++) {
                uint32_t* p = Bw + (bkb + ii * 8) * GST + bn4;
                p[0] = f2tf(rb[ii].x); p[1] = f2tf(rb[ii].y);
                p[2] = f2tf(rb[ii].z); p[3] = f2tf(rb[ii].w);
            }
            __syncthreads();
            buf = nb;
        }
    }

    // epilogue with bias
#pragma unroll
    for (int i = 0; i < 4; i++) {
        const int r0 = bm + warpm + i * 16 + g;
#pragma unroll
        for (int j = 0; j < 4; j++) {
            const int c0 = bn + warpn + j * 8 + 2 * t;
            const float b0 = bias[c0], b1 = bias[c0 + 1];
            if (r0 < M) {
                float2 v; v.x = acc[i][j][0] + b0; v.y = acc[i][j][1] + b1;
                *(float2*)(C + (size_t)r0 * N + c0) = v;
            }
            if (r0 + 8 < M) {
                float2 v; v.x = acc[i][j][2] + b0; v.y = acc[i][j][3] + b1;
                *(float2*)(C + (size_t)(r0 + 8) * N + c0) = v;
            }
        }
    }
}

// ---------------- RMSNorm (over full DIM) + RoPE + layout to [h][s][d] --------
__global__ void __launch_bounds__(256) norm_rope(
    const float* __restrict__ gamma_q, const float* __restrict__ gamma_k,
    const float* __restrict__ cosb, const float* __restrict__ sinb)
{
    const int s = blockIdx.x;
    const int tid = threadIdx.x;
    __shared__ float row[DIM];
    __shared__ float red[8];
    __shared__ float s_scale;

    const float* base = buf_qkv + (size_t)s * NQKV;

    for (int sel = 0; sel < 2; sel++) {
        const float* src = base + sel * DIM;
        const float* gamma = sel ? gamma_k : gamma_q;
        float* dst = sel ? buf_k : buf_q;

        float ss = 0.f;
        for (int j = tid; j < DIM; j += 256) {
            float x = src[j];
            row[j] = x;
            ss += x * x;
        }
#pragma unroll
        for (int off = 16; off > 0; off >>= 1)
            ss += __shfl_xor_sync(0xffffffffu, ss, off);
        if ((tid & 31) == 0) red[tid >> 5] = ss;
        __syncthreads();
        if (tid == 0) {
            float tt = 0.f;
#pragma unroll
            for (int wq = 0; wq < 8; wq++) tt += red[wq];
            s_scale = rsqrtf(tt / (float)DIM + 1e-6f);
        }
        __syncthreads();
        const float scale = s_scale;

        for (int j2 = tid; j2 < DIM / 2; j2 += 256) {
            float x1 = row[2 * j2]     * scale * gamma[2 * j2];
            float x2 = row[2 * j2 + 1] * scale * gamma[2 * j2 + 1];
            const int i = j2 & 63;
            const float c  = cosb[s * 64 + i];
            const float sn = sinb[s * 64 + i];
            const int h = (2 * j2) >> 7;
            const int d = (2 * j2) & 127;
            dst[((size_t)h * SEQ + s) * HD + d]     = x1 * c - x2 * sn;
            dst[((size_t)h * SEQ + s) * HD + d + 1] = x1 * sn + x2 * c;
        }
        __syncthreads();
    }

    const float* srcv = base + 2 * DIM;
    for (int j = tid; j < DIM; j += 256) {
        const int h = j >> 7, d = j & 127;
        buf_v[((size_t)h * SEQ + s) * HD + d] = srcv[j];
    }
}

// ---------------- TF32 flash attention, block-causal --------------------------
// BQ=64, BK=64, 128 threads (4 warps, 16 q-rows each). Q in registers (tf32
// a-frags, pre-scaled). K/V share one smem buffer; P re-fragments via smem.
// K phase uses stride 132 (banks 4g+t, conflict-free for QK^T B-frags);
// V phase uses stride 136 (banks 8t+g, conflict-free for PV B-frags).
#define ATT_BQ 64
#define KST 132
#define VST 136
#define PST 68
#define ATT_SMEM ((64 * VST + 64 * PST) * 4)

__global__ void __launch_bounds__(128) flash_tf32()
{
    extern __shared__ uint32_t sma[];
    uint32_t* KVs = sma;                // K: [64][132] / V: [64][136]
    uint32_t* Ps  = sma + 64 * VST;     // [64][68]

    const int h = blockIdx.y;
    const int q0 = blockIdx.x * ATT_BQ;
    const int tid = threadIdx.x, w = tid >> 5, lane = tid & 31;
    const int g = lane >> 2, t = lane & 3;

    const float* Qg = buf_q + (size_t)h * SEQ * HD;
    const float* Kg = buf_k + (size_t)h * SEQ * HD;
    const float* Vg = buf_v + (size_t)h * SEQ * HD;

    const int r0 = q0 + w * 16 + g, r1 = r0 + 8;
    const int lr0 = w * 16 + g, lr1 = lr0 + 8;
    const float sc = 0.08838834764831845f;   // 1/sqrt(128)

    // Q a-frags, pre-scaled, tf32 (HD/8 = 16 k-steps)
    uint32_t qa[16][4];
#pragma unroll
    for (int ks = 0; ks < 16; ks++) {
        const int k8 = ks * 8;
        qa[ks][0] = (r0 < SEQ) ? f2tf(Qg[(size_t)r0 * HD + k8 + t] * sc) : 0u;
        qa[ks][1] = (r1 < SEQ) ? f2tf(Qg[(size_t)r1 * HD + k8 + t] * sc) : 0u;
        qa[ks][2] = (r0 < SEQ) ? f2tf(Qg[(size_t)r0 * HD + k8 + t + 4] * sc) : 0u;
        qa[ks][3] = (r1 < SEQ) ? f2tf(Qg[(size_t)r1 * HD + k8 + t + 4] * sc) : 0u;
    }

    float O[16][4];
#pragma unroll
    for (int j = 0; j < 16; j++)
#pragma unroll
        for (int c = 0; c < 4; c++) O[j][c] = 0.f;
    float m0 = -1e30f, m1 = -1e30f, l0 = 0.f, l1 = 0.f;

    int rl0 = (r0 / FRAME + 1) * FRAME; if (rl0 > SEQ) rl0 = SEQ;
    int rl1 = (r1 / FRAME + 1) * FRAME; if (rl1 > SEQ) rl1 = SEQ;
    int qlast = q0 + ATT_BQ - 1; if (qlast > SEQ - 1) qlast = SEQ - 1;
    int kmax = (qlast / FRAME + 1) * FRAME; if (kmax > SEQ) kmax = SEQ;

    for (int k0 = 0; k0 < kmax; k0 += 64) {
        // load K tile (cvt to tf32): KVs[key][d], stride KST
        for (int idx = tid; idx < 64 * 32; idx += 128) {
            const int r = idx >> 5, c4 = (idx & 31) << 2;
            const int srow = k0 + r;
            float4 v = (srow < SEQ) ? *(const float4*)(Kg + (size_t)srow * HD + c4)
                                    : make_float4(0.f, 0.f, 0.f, 0.f);
            uint32_t* p = KVs + r * KST + c4;
            p[0] = f2tf(v.x); p[1] = f2tf(v.y); p[2] = f2tf(v.z); p[3] = f2tf(v.w);
        }
        __syncthreads();

        // S = Q K^T (per warp: 16 rows x 64 cols, 8 n-tiles)
        float sf[8][4];
#pragma unroll
        for (int j = 0; j < 8; j++)
#pragma unroll
            for (int c = 0; c < 4; c++) sf[j][c] = 0.f;

#pragma unroll
        for (int ks = 0; ks < 16; ks++) {
            const int k8 = ks * 8;
#pragma unroll
            for (int j = 0; j < 8; j++) {
                uint32_t bf[2];
                const uint32_t* kp = KVs + (j * 8 + g) * KST + k8 + t;
                bf[0] = kp[0]; bf[1] = kp[4];
                mma8(sf[j], qa[ks], bf);
            }
        }

        // mask + online softmax
        float mt0 = -1e30f, mt1 = -1e30f;
#pragma unroll
        for (int j = 0; j < 8; j++) {
            const int c = k0 + j * 8 + 2 * t;
            sf[j][0] = (c     < rl0) ? sf[j][0] : -1e30f;
            sf[j][1] = (c + 1 < rl0) ? sf[j][1] : -1e30f;
            sf[j][2] = (c     < rl1) ? sf[j][2] : -1e30f;
            sf[j][3] = (c + 1 < rl1) ? sf[j][3] : -1e30f;
            mt0 = fmaxf(mt0, fmaxf(sf[j][0], sf[j][1]));
            mt1 = fmaxf(mt1, fmaxf(sf[j][2], sf[j][3]));
        }
        mt0 = fmaxf(mt0, __shfl_xor_sync(0xffffffffu, mt0, 1));
        mt0 = fmaxf(mt0, __shfl_xor_sync(0xffffffffu, mt0, 2));
        mt1 = fmaxf(mt1, __shfl_xor_sync(0xffffffffu, mt1, 1));
        mt1 = fmaxf(mt1, __shfl_xor_sync(0xffffffffu, mt1, 2));

        const float mn0 = fmaxf(m0, mt0), mn1 = fmaxf(m1, mt1);
        const float a0 = __expf(m0 - mn0), a1 = __expf(m1 - mn1);
        float s0 = 0.f, s1 = 0.f;
#pragma unroll
        for (int j = 0; j < 8; j++) {
            float p0 = __expf(sf[j][0] - mn0);
            float p1 = __expf(sf[j][1] - mn0);
            float p2 = __expf(sf[j][2] - mn1);
            float p3 = __expf(sf[j][3] - mn1);
            s0 += p0 + p1; s1 += p2 + p3;
            uint32_t* pp0 = Ps + lr0 * PST + j * 8 + 2 * t;
            uint32_t* pp1 = Ps + lr1 * PST + j * 8 + 2 * t;
            pp0[0] = f2tf(p0); pp0[1] = f2tf(p1);
            pp1[0] = f2tf(p2); pp1[1] = f2tf(p3);
        }
        s0 += __shfl_xor_sync(0xffffffffu, s0, 1);
        s0 += __shfl_xor_sync(0xffffffffu, s0, 2);
        s1 += __shfl_xor_sync(0xffffffffu, s1, 1);
        s1 += __shfl_xor_sync(0xffffffffu, s1, 2);
        l0 = l0 * a0 + s0;  m0 = mn0;
        l1 = l1 * a1 + s1;  m1 = mn1;
#pragma unroll
        for (int j = 0; j < 16; j++) {
            O[j][0] *= a0; O[j][1] *= a0;
            O[j][2] *= a1; O[j][3] *= a1;
        }
        __syncthreads();   // all warps done reading K

        // load V tile (cvt to tf32) over KVs, stride VST
        for (int idx = tid; idx < 64 * 32; idx += 128) {
            const int r = idx >> 5, c4 = (idx & 31) << 2;
            const int srow = k0 + r;
            float4 v = (srow < SEQ) ? *(const float4*)(Vg + (size_t)srow * HD + c4)
                                    : make_float4(0.f, 0.f, 0.f, 0.f);
            uint32_t* p = KVs + r * VST + c4;
            p[0] = f2tf(v.x); p[1] = f2tf(v.y); p[2] = f2tf(v.z); p[3] = f2tf(v.w);
        }
        __syncthreads();

        // O += P @ V
#pragma unroll
        for (int kk = 0; kk < 8; kk++) {
            const int k8 = kk * 8;
            uint32_t af[4];
            const uint32_t* p0 = Ps + lr0 * PST + k8 + t;
            const uint32_t* p1 = Ps + lr1 * PST + k8 + t;
            af[0] = p0[0]; af[1] = p1[0]; af[2] = p0[4]; af[3] = p1[4];
#pragma unroll
            for (int j = 0; j < 16; j++) {
                uint32_t bf[2];
                const uint32_t* vp = KVs + (k8 + t) * VST + j * 8 + g;
                bf[0] = vp[0]; bf[1] = vp[4 * VST];
                mma8(O[j], af, bf);
            }
        }
        __syncthreads();   // before next tile overwrites KVs
    }

    // epilogue
    const float inv0 = 1.f / l0, inv1 = 1.f / l1;
#pragma unroll
    for (int j = 0; j < 16; j++) {
        const int c = h * HD + j * 8 + 2 * t;
        if (r0 < SEQ) {
            float2 v; v.x = O[j][0] * inv0; v.y = O[j][1] * inv0;
            *(float2*)(buf_att + (size_t)r0 * DIM + c) = v;
        }
        if (r1 < SEQ) {
            float2 v; v.x = O[j][2] * inv1; v.y = O[j][3] * inv1;
            *(float2*)(buf_att + (size_t)r1 * DIM + c) = v;
        }
    }
}

// ---------------- launch ------------------------------------------------------
extern "C" void kernel_launch(void* const* d_in, const int* in_sizes, int n_in,
                              void* d_out, int out_size)
{
    const float* hidden  = (const float*)d_in[0];
    const float* cosb    = (const float*)d_in[1];
    const float* sinb    = (const float*)d_in[2];
    const float* w_qkv   = (const float*)d_in[3];
    const float* b_qkv   = (const float*)d_in[4];
    const float* gamma_q = (const float*)d_in[5];
    const float* gamma_k = (const float*)d_in[6];
    const float* w_out   = (const float*)d_in[7];
    const float* b_out   = (const float*)d_in[8];
    float* out = (float*)d_out;

    float *qkv_p, *att_p;
    cudaGetSymbolAddress((void**)&qkv_p, buf_qkv);
    cudaGetSymbolAddress((void**)&att_p, buf_att);

    cudaFuncSetAttribute(gemm_tf32, cudaFuncAttributeMaxDynamicSharedMemorySize,
                         GEMM_SMEM);
    cudaFuncSetAttribute(flash_tf32, cudaFuncAttributeMaxDynamicSharedMemorySize,
                         ATT_SMEM);

    // 1) QKV projection
    dim3 g1(NQKV / 128, (SEQ + 127) / 128);
    gemm_tf32<<<g1, 256, GEMM_SMEM>>>(SEQ, NQKV, DIM, hidden, w_qkv, b_qkv, qkv_p);

    // 2) RMSNorm + RoPE + relayout
    norm_rope<<<SEQ, 256>>>(gamma_q, gamma_k, cosb, sinb);

    // 3) attention
    dim3 g3((SEQ + ATT_BQ - 1) / ATT_BQ, NH);
    flash_tf32<<<g3, 128, ATT_SMEM>>>();

    // 4) output projection
    dim3 g4(DIM / 128, (SEQ + 127) / 128);
    gemm_tf32<<<g4, 256, GEMM_SMEM>>>(SEQ, DIM, DIM, att_p, w_out, b_out, out);
}

// round 4
// speedup vs baseline: 3.4742x; 1.2679x over previous
#include <cuda_runtime.h>
#include <cstdint>

#define SEQ 3120
#define DIM 1536
#define NH 12
#define HD 128
#define FRAME 1560
#define NQKV (3*DIM)

// ---------------- scratch (device globals; no allocation allowed) -------------
__device__ float buf_qkv[(size_t)SEQ * NQKV];
__device__ float buf_q[(size_t)NH * SEQ * HD];     // [h][s][d], tf32-rounded, pre-scaled
__device__ float buf_k[(size_t)NH * SEQ * HD];     // tf32-rounded
__device__ float buf_v[(size_t)NH * SEQ * HD];     // tf32-rounded
__device__ float buf_att[(size_t)SEQ * DIM];       // [s][h*128+d], tf32-rounded
__device__ float buf_xc[(size_t)SEQ * DIM];        // tf32(hidden)
__device__ float buf_wqc[(size_t)DIM * NQKV];      // tf32(w_qkv)
__device__ float buf_woc[(size_t)DIM * DIM];       // tf32(w_out)

// ---------------- helpers -----------------------------------------------------
__device__ __forceinline__ uint32_t f2tf(float x) {
    uint32_t u;
    asm("cvt.rna.tf32.f32 %0, %1;" : "=r"(u) : "f"(x));
    return u;
}

__device__ __forceinline__ void mma8(float* d, const uint32_t* a, const uint32_t* b) {
    asm volatile(
        "mma.sync.aligned.m16n8k8.row.col.f32.tf32.tf32.f32 "
        "{%0,%1,%2,%3},{%4,%5,%6,%7},{%8,%9},{%0,%1,%2,%3};"
        : "+f"(d[0]), "+f"(d[1]), "+f"(d[2]), "+f"(d[3])
        : "r"(a[0]), "r"(a[1]), "r"(a[2]), "r"(a[3]), "r"(b[0]), "r"(b[1]));
}

__device__ __forceinline__ void cpa16(uint32_t s, const void* g, bool v) {
    asm volatile("cp.async.ca.shared.global [%0], [%1], 16, %2;"
                 :: "r"(s), "l"(g), "r"(v ? 16 : 0));
}
__device__ __forceinline__ void cpcommit() {
    asm volatile("cp.async.commit_group;");
}
template<int N> __device__ __forceinline__ void cpwait() {
    asm volatile("cp.async.wait_group %0;" :: "n"(N));
}

// ---------------- tf32 rounding pre-pass --------------------------------------
__global__ void __launch_bounds__(256) cvt_tf32(
    const float* __restrict__ in, float* __restrict__ out, int n4)
{
    int i = blockIdx.x * 256 + threadIdx.x;
    if (i < n4) {
        float4 v = ((const float4*)in)[i];
        v.x = __uint_as_float(f2tf(v.x));
        v.y = __uint_as_float(f2tf(v.y));
        v.z = __uint_as_float(f2tf(v.z));
        v.w = __uint_as_float(f2tf(v.w));
        ((float4*)out)[i] = v;
    }
}

// ---------------- TF32 GEMM with cp.async 3-stage pipeline --------------------
// C[M,N] = A[M,K] @ B[K,N] + bias. A,B pre-rounded to tf32 values.
// 128x128x32 tile, 256 threads (8 warps 2x4, warp tile 64x32).
// smem: A m-major [128][36], B n-major [32][132]; both frag-conflict-free.
#define GK 32
#define AST 36
#define BST 132
#define STAGE_ELE (128*AST + 32*BST)
#define GEMM_SMEM (3 * STAGE_ELE * 4)

__global__ void __launch_bounds__(256, 2) gemm_tf32(
    int M, int N, int K,
    const float* __restrict__ A, const float* __restrict__ B,
    const float* __restrict__ bias, float* __restrict__ C)
{
    extern __shared__ float smg[];

    const int tid = threadIdx.x;
    const int wid = tid >> 5, lane = tid & 31;
    const int g = lane >> 2, t = lane & 3;
    const int bm = blockIdx.y * 128, bn = blockIdx.x * 128;
    const int warpm = (wid >> 2) * 64, warpn = (wid & 3) * 32;

    // loader mapping
    const int ar = tid >> 1;            // A row 0..127
    const int ac = (tid & 1) * 16;      // A col base (0 / 16)
    const int br = tid >> 3;            // B k-row 0..31
    const int bc = (tid & 7) * 16;      // B col base
    const bool aval = (bm + ar) < M;
    const float* Ag = A + (size_t)(bm + ar) * K + ac;
    const float* Bg = B + (size_t)br * N + bn + bc;

    auto issue = [&](int st, int kt) {
        float* As = smg + st * STAGE_ELE;
        float* Bs = As + 128 * AST;
        uint32_t sa = (uint32_t)__cvta_generic_to_shared(As + ar * AST + ac);
        const float* ga = Ag + kt * GK;
#pragma unroll
        for (int c = 0; c < 4; c++)
            cpa16(sa + c * 16, ga + c * 4, aval);
        uint32_t sb = (uint32_t)__cvta_generic_to_shared(Bs + br * BST + bc);
        const float* gb = Bg + (size_t)kt * GK * N;
#pragma unroll
        for (int c = 0; c < 4; c++)
            cpa16(sb + c * 16, gb + c * 4, true);
    };

    float acc[4][4][4];
#pragma unroll
    for (int i = 0; i < 4; i++)
#pragma unroll
        for (int j = 0; j < 4; j++)
#pragma unroll
            for (int c = 0; c < 4; c++) acc[i][j][c] = 0.f;

    const int KT = K / GK;

    issue(0, 0); cpcommit();
    issue(1, 1); cpcommit();

    for (int kt = 0; kt < KT; kt++) {
        cpwait<1>();
        __syncthreads();

        const uint32_t* Ab = (const uint32_t*)(smg + (kt % 3) * STAGE_ELE);
        const uint32_t* Bb = Ab + 128 * AST;

#pragma unroll
        for (int kk = 0; kk < 4; kk++) {
            const int k8 = kk * 8;
            uint32_t af[4][4], bf[4][2];
#pragma unroll
            for (int i = 0; i < 4; i++) {
                const int m0 = warpm + i * 16 + g;
                af[i][0] = Ab[m0 * AST + k8 + t];
                af[i][1] = Ab[(m0 + 8) * AST + k8 + t];
                af[i][2] = Ab[m0 * AST + k8 + t + 4];
                af[i][3] = Ab[(m0 + 8) * AST + k8 + t + 4];
            }
#pragma unroll
            for (int j = 0; j < 4; j++) {
                bf[j][0] = Bb[(k8 + t) * BST + warpn + j * 8 + g];
                bf[j][1] = Bb[(k8 + t + 4) * BST + warpn + j * 8 + g];
            }
#pragma unroll
            for (int i = 0; i < 4; i++)
#pragma unroll
                for (int j = 0; j < 4; j++)
                    mma8(acc[i][j], af[i], bf[j]);
        }

        if (kt + 2 < KT) issue((kt + 2) % 3, kt + 2);
        cpcommit();
    }

    // epilogue with bias
#pragma unroll
    for (int i = 0; i < 4; i++) {
        const int r0 = bm + warpm + i * 16 + g;
#pragma unroll
        for (int j = 0; j < 4; j++) {
            const int c0 = bn + warpn + j * 8 + 2 * t;
            const float b0 = bias[c0], b1 = bias[c0 + 1];
            if (r0 < M) {
                float2 v; v.x = acc[i][j][0] + b0; v.y = acc[i][j][1] + b1;
                *(float2*)(C + (size_t)r0 * N + c0) = v;
            }
            if (r0 + 8 < M) {
                float2 v; v.x = acc[i][j][2] + b0; v.y = acc[i][j][3] + b1;
                *(float2*)(C + (size_t)(r0 + 8) * N + c0) = v;
            }
        }
    }
}

// ---------------- RMSNorm + RoPE + relayout; outputs tf32-rounded -------------
__global__ void __launch_bounds__(256) norm_rope(
    const float* __restrict__ gamma_q, const float* __restrict__ gamma_k,
    const float* __restrict__ cosb, const float* __restrict__ sinb)
{
    const int s = blockIdx.x;
    const int tid = threadIdx.x;
    __shared__ float row[DIM];
    __shared__ float red[8];
    __shared__ float s_scale;

    const float* base = buf_qkv + (size_t)s * NQKV;
    const float qsc = 0.08838834764831845f;  // 1/sqrt(128)

    for (int sel = 0; sel < 2; sel++) {
        const float* src = base + sel * DIM;
        const float* gamma = sel ? gamma_k : gamma_q;
        float* dst = sel ? buf_k : buf_q;
        const float post = sel ? 1.f : qsc;

        float ss = 0.f;
        for (int j = tid; j < DIM; j += 256) {
            float x = src[j];
            row[j] = x;
            ss += x * x;
        }
#pragma unroll
        for (int off = 16; off > 0; off >>= 1)
            ss += __shfl_xor_sync(0xffffffffu, ss, off);
        if ((tid & 31) == 0) red[tid >> 5] = ss;
        __syncthreads();
        if (tid == 0) {
            float tt = 0.f;
#pragma unroll
            for (int wq = 0; wq < 8; wq++) tt += red[wq];
            s_scale = rsqrtf(tt / (float)DIM + 1e-6f);
        }
        __syncthreads();
        const float scale = s_scale;

        for (int j2 = tid; j2 < DIM / 2; j2 += 256) {
            float x1 = row[2 * j2]     * scale * gamma[2 * j2];
            float x2 = row[2 * j2 + 1] * scale * gamma[2 * j2 + 1];
            const int i = j2 & 63;
            const float c  = cosb[s * 64 + i];
            const float sn = sinb[s * 64 + i];
            const int h = (2 * j2) >> 7;
            const int d = (2 * j2) & 127;
            dst[((size_t)h * SEQ + s) * HD + d] =
                __uint_as_float(f2tf((x1 * c - x2 * sn) * post));
            dst[((size_t)h * SEQ + s) * HD + d + 1] =
                __uint_as_float(f2tf((x1 * sn + x2 * c) * post));
        }
        __syncthreads();
    }

    const float* srcv = base + 2 * DIM;
    for (int j = tid; j < DIM; j += 256) {
        const int h = j >> 7, d = j & 127;
        buf_v[((size_t)h * SEQ + s) * HD + d] = __uint_as_float(f2tf(srcv[j]));
    }
}

// ---------------- TF32 flash attention with cp.async prefetch -----------------
// BQ=64, BK=64, 128 threads (4 warps). Q (pre-scaled tf32) in regs.
// Separate K [64][132] / V [64][136] smem buffers; cross-tile cp.async
// prefetch: K_{i+1} issued during PV_i, V_{i+1} after PV_i.
#define ATT_BQ 64
#define KST 132
#define VST 136
#define PST 68
#define ATT_SMEM ((64*KST + 64*VST + 64*PST) * 4)

__global__ void __launch_bounds__(128) flash_tf32()
{
    extern __shared__ float sma[];
    float* Kb = sma;                       // [64][132]
    float* Vb = sma + 64 * KST;            // [64][136]
    uint32_t* Ps = (uint32_t*)(sma + 64 * KST + 64 * VST);  // [64][68]

    const int h = blockIdx.y;
    const int q0 = blockIdx.x * ATT_BQ;
    const int tid = threadIdx.x, w = tid >> 5, lane = tid & 31;
    const int g = lane >> 2, t = lane & 3;

    const uint32_t* Qg = (const uint32_t*)(buf_q + (size_t)h * SEQ * HD);
    const float* Kg = buf_k + (size_t)h * SEQ * HD;
    const float* Vg = buf_v + (size_t)h * SEQ * HD;

    const int r0 = q0 + w * 16 + g, r1 = r0 + 8;
    const int lr0 = w * 16 + g, lr1 = lr0 + 8;

    auto issueK = [&](int k0) {
#pragma unroll 4
        for (int i = tid; i < 64 * 32; i += 128) {
            const int r = i >> 5, c4 = (i & 31) << 2;
            const int srow = k0 + r;
            uint32_t s = (uint32_t)__cvta_generic_to_shared(Kb + r * KST + c4);
            cpa16(s, Kg + (size_t)srow * HD + c4, srow < SEQ);
        }
    };
    auto issueV = [&](int k0) {
#pragma unroll 4
        for (int i = tid; i < 64 * 32; i += 128) {
            const int r = i >> 5, c4 = (i & 31) << 2;
            const int srow = k0 + r;
            uint32_t s = (uint32_t)__cvta_generic_to_shared(Vb + r * VST + c4);
            cpa16(s, Vg + (size_t)srow * HD + c4, srow < SEQ);
        }
    };

    // Q a-frags (already tf32-rounded and scaled)
    uint32_t qa[16][4];
#pragma unroll
    for (int ks = 0; ks < 16; ks++) {
        const int k8 = ks * 8;
        qa[ks][0] = (r0 < SEQ) ? Qg[(size_t)r0 * HD + k8 + t] : 0u;
        qa[ks][1] = (r1 < SEQ) ? Qg[(size_t)r1 * HD + k8 + t] : 0u;
        qa[ks][2] = (r0 < SEQ) ? Qg[(size_t)r0 * HD + k8 + t + 4] : 0u;
        qa[ks][3] = (r1 < SEQ) ? Qg[(size_t)r1 * HD + k8 + t + 4] : 0u;
    }

    float O[16][4];
#pragma unroll
    for (int j = 0; j < 16; j++)
#pragma unroll
        for (int c = 0; c < 4; c++) O[j][c] = 0.f;
    float m0 = -1e30f, m1 = -1e30f, l0 = 0.f, l1 = 0.f;

    int rl0 = (r0 / FRAME + 1) * FRAME; if (rl0 > SEQ) rl0 = SEQ;
    int rl1 = (r1 / FRAME + 1) * FRAME; if (rl1 > SEQ) rl1 = SEQ;
    int qlast = q0 + ATT_BQ - 1; if (qlast > SEQ - 1) qlast = SEQ - 1;
    int kmax = (qlast / FRAME + 1) * FRAME; if (kmax > SEQ) kmax = SEQ;

    issueK(0); cpcommit();
    issueV(0); cpcommit();

    for (int k0 = 0; k0 < kmax; k0 += 64) {
        cpwait<1>();           // K tile ready
        __syncthreads();

        // S = Q K^T
        float sf[8][4];
#pragma unroll
        for (int j = 0; j < 8; j++)
#pragma unroll
            for (int c = 0; c < 4; c++) sf[j][c] = 0.f;

        const uint32_t* Kbu = (const uint32_t*)Kb;
#pragma unroll
        for (int ks = 0; ks < 16; ks++) {
            const int k8 = ks * 8;
#pragma unroll
            for (int j = 0; j < 8; j++) {
                uint32_t bf[2];
                const uint32_t* kp = Kbu + (j * 8 + g) * KST + k8 + t;
                bf[0] = kp[0]; bf[1] = kp[4];
                mma8(sf[j], qa[ks], bf);
            }
        }

        // mask + online softmax
        float mt0 = -1e30f, mt1 = -1e30f;
#pragma unroll
        for (int j = 0; j < 8; j++) {
            const int c = k0 + j * 8 + 2 * t;
            sf[j][0] = (c     < rl0) ? sf[j][0] : -1e30f;
            sf[j][1] = (c + 1 < rl0) ? sf[j][1] : -1e30f;
            sf[j][2] = (c     < rl1) ? sf[j][2] : -1e30f;
            sf[j][3] = (c + 1 < rl1) ? sf[j][3] : -1e30f;
            mt0 = fmaxf(mt0, fmaxf(sf[j][0], sf[j][1]));
            mt1 = fmaxf(mt1, fmaxf(sf[j][2], sf[j][3]));
        }
        mt0 = fmaxf(mt0, __shfl_xor_sync(0xffffffffu, mt0, 1));
        mt0 = fmaxf(mt0, __shfl_xor_sync(0xffffffffu, mt0, 2));
        mt1 = fmaxf(mt1, __shfl_xor_sync(0xffffffffu, mt1, 1));
        mt1 = fmaxf(mt1, __shfl_xor_sync(0xffffffffu, mt1, 2));

        const float mn0 = fmaxf(m0, mt0), mn1 = fmaxf(m1, mt1);
        const float a0 = __expf(m0 - mn0), a1 = __expf(m1 - mn1);
        float s0 = 0.f, s1 = 0.f;
#pragma unroll
        for (int j = 0; j < 8; j++) {
            float p0 = __expf(sf[j][0] - mn0);
            float p1 = __expf(sf[j][1] - mn0);
            float p2 = __expf(sf[j][2] - mn1);
            float p3 = __expf(sf[j][3] - mn1);
            s0 += p0 + p1; s1 += p2 + p3;
            uint32_t* pp0 = Ps + lr0 * PST + j * 8 + 2 * t;
            uint32_t* pp1 = Ps + lr1 * PST + j * 8 + 2 * t;
            pp0[0] = f2tf(p0); pp0[1] = f2tf(p1);
            pp1[0] = f2tf(p2); pp1[1] = f2tf(p3);
        }
        s0 += __shfl_xor_sync(0xffffffffu, s0, 1);
        s0 += __shfl_xor_sync(0xffffffffu, s0, 2);
        s1 += __shfl_xor_sync(0xffffffffu, s1, 1);
        s1 += __shfl_xor_sync(0xffffffffu, s1, 2);
        l0 = l0 * a0 + s0;  m0 = mn0;
        l1 = l1 * a1 + s1;  m1 = mn1;
#pragma unroll
        for (int j = 0; j < 16; j++) {
            O[j][0] *= a0; O[j][1] *= a0;
            O[j][2] *= a1; O[j][3] *= a1;
        }

        cpwait<0>();           // V tile ready; sync also covers Ps writes
        __syncthreads();

        // prefetch next K (overlaps PV)
        if (k0 + 64 < kmax) issueK(k0 + 64);
        cpcommit();

        // O += P @ V
        const uint32_t* Vbu = (const uint32_t*)Vb;
#pragma unroll
        for (int kk = 0; kk < 8; kk++) {
            const int k8 = kk * 8;
            uint32_t af[4];
            const uint32_t* p0 = Ps + lr0 * PST + k8 + t;
            const uint32_t* p1 = Ps + lr1 * PST + k8 + t;
            af[0] = p0[0]; af[1] = p1[0]; af[2] = p0[4]; af[3] = p1[4];
#pragma unroll
            for (int j = 0; j < 16; j++) {
                uint32_t bf[2];
                const uint32_t* vp = Vbu + (k8 + t) * VST + j * 8 + g;
                bf[0] = vp[0]; bf[1] = vp[4 * VST];
                mma8(O[j], af, bf);
            }
        }
        __syncthreads();       // all warps done with Vb / Ps

        // prefetch next V (overlaps next QK)
        if (k0 + 64 < kmax) issueV(k0 + 64);
        cpcommit();
    }

    // epilogue: tf32-round so out-proj reads pre-converted A
    const float inv0 = 1.f / l0, inv1 = 1.f / l1;
#pragma unroll
    for (int j = 0; j < 16; j++) {
        const int c = h * HD + j * 8 + 2 * t;
        if (r0 < SEQ) {
            float2 v;
            v.x = __uint_as_float(f2tf(O[j][0] * inv0));
            v.y = __uint_as_float(f2tf(O[j][1] * inv0));
            *(float2*)(buf_att + (size_t)r0 * DIM + c) = v;
        }
        if (r1 < SEQ) {
            float2 v;
            v.x = __uint_as_float(f2tf(O[j][2] * inv1));
            v.y = __uint_as_float(f2tf(O[j][3] * inv1));
            *(float2*)(buf_att + (size_t)r1 * DIM + c) = v;
        }
    }
}

// ---------------- launch ------------------------------------------------------
extern "C" void kernel_launch(void* const* d_in, const int* in_sizes, int n_in,
                              void* d_out, int out_size)
{
    const float* hidden  = (const float*)d_in[0];
    const float* cosb    = (const float*)d_in[1];
    const float* sinb    = (const float*)d_in[2];
    const float* w_qkv   = (const float*)d_in[3];
    const float* b_qkv   = (const float*)d_in[4];
    const float* gamma_q = (const float*)d_in[5];
    const float* gamma_k = (const float*)d_in[6];
    const float* w_out   = (const float*)d_in[7];
    const float* b_out   = (const float*)d_in[8];
    float* out = (float*)d_out;

    float *qkv_p, *att_p, *xc_p, *wqc_p, *woc_p;
    cudaGetSymbolAddress((void**)&qkv_p, buf_qkv);
    cudaGetSymbolAddress((void**)&att_p, buf_att);
    cudaGetSymbolAddress((void**)&xc_p,  buf_xc);
    cudaGetSymbolAddress((void**)&wqc_p, buf_wqc);
    cudaGetSymbolAddress((void**)&woc_p, buf_woc);

    cudaFuncSetAttribute(gemm_tf32, cudaFuncAttributeMaxDynamicSharedMemorySize,
                         GEMM_SMEM);
    cudaFuncSetAttribute(flash_tf32, cudaFuncAttributeMaxDynamicSharedMemorySize,
                         ATT_SMEM);

    // 0) tf32 rounding pre-pass (bandwidth-trivial)
    int n4;
    n4 = SEQ * DIM / 4;
    cvt_tf32<<<(n4 + 255) / 256, 256>>>(hidden, xc_p, n4);
    n4 = DIM * NQKV / 4;
    cvt_tf32<<<(n4 + 255) / 256, 256>>>(w_qkv, wqc_p, n4);
    n4 = DIM * DIM / 4;
    cvt_tf32<<<(n4 + 255) / 256, 256>>>(w_out, woc_p, n4);

    // 1) QKV projection
    dim3 g1(NQKV / 128, (SEQ + 127) / 128);
    gemm_tf32<<<g1, 256, GEMM_SMEM>>>(SEQ, NQKV, DIM, xc_p, wqc_p, b_qkv, qkv_p);

    // 2) RMSNorm + RoPE + relayout (tf32-rounded outputs)
    norm_rope<<<SEQ, 256>>>(gamma_q, gamma_k, cosb, sinb);

    // 3) attention
    dim3 g3((SEQ + ATT_BQ - 1) / ATT_BQ, NH);
    flash_tf32<<<g3, 128, ATT_SMEM>>>();

    // 4) output projection
    dim3 g4(DIM / 128, (SEQ + 127) / 128);
    gemm_tf32<<<g4, 256, GEMM_SMEM>>>(SEQ, DIM, DIM, att_p, woc_p, b_out, out);
}